// round 16
// baseline (speedup 1.0000x reference)
#include <cuda_runtime.h>
#include <cuda_bf16.h>
#include <cuda_fp16.h>
#include <math.h>
#include <stdint.h>

#define NMAX 100000
#define EMAX 1600000
#define DD 64
#define NGR 16
#define TR 128
#define TB 256
#define SA 72              // bf16 row stride for A/W smem tiles

// k_fused dynamic smem: A0hi A0lo A1hi A1lo W0hi W0lo W1hi W1lo
// (A1 space is reused for the softmax buckets after phase 1b)
#define OFF_A0HI 0
#define OFF_A0LO 18432
#define OFF_A1HI 36864
#define OFF_A1LO 55296
#define OFF_W0HI 73728
#define OFF_W0LO 82944
#define OFF_W1HI 92160
#define OFF_W1LO 101376
#define DYN_FUSED 110592
#define DYN_Y 55296

// ---------------- device scratch ----------------
__device__ __half g_y[(size_t)NMAX * DD];     // fp16 messages
__device__ float g_agg[(size_t)NMAX * DD];
__device__ int   g_deg[NMAX];
__device__ int   g_offs[NMAX];
__device__ int   g_cursor[NMAX];
__device__ int   g_src[EMAX];
__device__ int   g_counter;
__device__ float g_P[NGR * DD];
__device__ float g_numvec[NGR * DD];          // sum e*feat
__device__ float g_denom[NGR];                // sum e
// weight images: [step][mat][hi 576 uint4 | lo 576 uint4]; mat: 0=Wa_x 1=Wa_a 2=Wfeat 3=Wm
__device__ uint4 g_wimg[4][4][1152];

__device__ __forceinline__ float lrelu(float v) { return v > 0.f ? v : 0.01f * v; }

__device__ __forceinline__ uint32_t sptr(const void* p) {
    uint32_t a;
    asm("{ .reg .u64 t; cvta.to.shared.u64 t, %1; cvt.u32.u64 %0, t; }" : "=r"(a) : "l"(p));
    return a;
}
__device__ __forceinline__ void cp16(uint32_t saddr, const void* gaddr) {
    asm volatile("cp.async.cg.shared.global [%0], [%1], 16;" :: "r"(saddr), "l"(gaddr));
}
#define CP_COMMIT() asm volatile("cp.async.commit_group;" ::: "memory")
#define CP_WAIT0()  asm volatile("cp.async.wait_group 0;" ::: "memory")

// ---------------- mma.sync building blocks ----------------
__device__ __forceinline__ void mma16816(float c[4], uint32_t a0, uint32_t a1,
                                         uint32_t a2, uint32_t a3,
                                         uint32_t b0, uint32_t b1) {
    asm volatile(
        "mma.sync.aligned.m16n8k16.row.col.f32.bf16.bf16.f32 "
        "{%0,%1,%2,%3}, {%4,%5,%6,%7}, {%8,%9}, {%0,%1,%2,%3};"
        : "+f"(c[0]), "+f"(c[1]), "+f"(c[2]), "+f"(c[3])
        : "r"(a0), "r"(a1), "r"(a2), "r"(a3), "r"(b0), "r"(b1));
}

// warp w computes rows w*16..w*16+15 x all 64 cols: c[8][4]   (R13 core)
__device__ __forceinline__ void wgemm(const __nv_bfloat16* A, const __nv_bfloat16* W,
                                      int w, int lane, float c[8][4]) {
#pragma unroll
    for (int kt = 0; kt < 64; kt += 16) {
        int kk = kt + ((lane & 3) << 1);
        uint32_t b0[8], b1[8];
#pragma unroll
        for (int j = 0; j < 8; j++) {
            int n = j * 8 + (lane >> 2);
            b0[j] = *(const uint32_t*)(W + n * SA + kk);
            b1[j] = *(const uint32_t*)(W + n * SA + kk + 8);
        }
        int r = w * 16 + (lane >> 2);
        uint32_t a0 = *(const uint32_t*)(A + r * SA + kk);
        uint32_t a1 = *(const uint32_t*)(A + (r + 8) * SA + kk);
        uint32_t a2 = *(const uint32_t*)(A + r * SA + kk + 8);
        uint32_t a3 = *(const uint32_t*)(A + (r + 8) * SA + kk + 8);
#pragma unroll
        for (int j = 0; j < 8; j++) mma16816(c[j], a0, a1, a2, a3, b0[j], b1[j]);
    }
}

__device__ __forceinline__ void gemm3(const __nv_bfloat16* Ahi, const __nv_bfloat16* Alo,
                                      const __nv_bfloat16* Whi, const __nv_bfloat16* Wlo,
                                      int w, int lane, float c[8][4]) {
    wgemm(Ahi, Whi, w, lane, c);
    wgemm(Alo, Whi, w, lane, c);
    wgemm(Ahi, Wlo, w, lane, c);
}

__device__ __forceinline__ void zero_c(float c[8][4]) {
#pragma unroll
    for (int j = 0; j < 8; j++)
#pragma unroll
        for (int q = 0; q < 4; q++) c[j][q] = 0.f;
}

// stream-convert half a global fp32 row into bf16 hi/lo smem (row r, half h)
__device__ __forceinline__ void conv_g(const float* src, __nv_bfloat16* Ahi,
                                       __nv_bfloat16* Alo, int r, int h, bool valid) {
#pragma unroll
    for (int qq = h * 4; qq < h * 4 + 4; qq++) {
        float v[8];
        if (valid) {
            float4 a = ((const float4*)src)[qq * 2];
            float4 b = ((const float4*)src)[qq * 2 + 1];
            v[0] = a.x; v[1] = a.y; v[2] = a.z; v[3] = a.w;
            v[4] = b.x; v[5] = b.y; v[6] = b.z; v[7] = b.w;
        } else {
#pragma unroll
            for (int i = 0; i < 8; i++) v[i] = 0.f;
        }
        uint32_t hh[4], ll[4];
#pragma unroll
        for (int j = 0; j < 4; j++) {
            __nv_bfloat162 hp = __floats2bfloat162_rn(v[2 * j], v[2 * j + 1]);
            hh[j] = *(uint32_t*)&hp;
            __nv_bfloat162 lp = __floats2bfloat162_rn(v[2 * j] - __bfloat162float(hp.x),
                                                      v[2 * j + 1] - __bfloat162float(hp.y));
            ll[j] = *(uint32_t*)&lp;
        }
        *(uint4*)(Ahi + r * SA + qq * 8) = make_uint4(hh[0], hh[1], hh[2], hh[3]);
        *(uint4*)(Alo + r * SA + qq * 8) = make_uint4(ll[0], ll[1], ll[2], ll[3]);
    }
}

// async W image load (hi 576 + lo 576 uint4)
__device__ __forceinline__ void load_wimg_ca(const uint4* img, uint32_t wHi, uint32_t wLo, int t) {
    for (int i = t; i < 576; i += TB) {
        cp16(wHi + i * 16, img + i);
        cp16(wLo + i * 16, img + 576 + i);
    }
}

// fragment -> fp16 global store
__device__ __forceinline__ void store_ch(__half* dst, int row0, int w, int lane,
                                         float c[8][4], int N) {
    int g = lane >> 2, q = lane & 3;
#pragma unroll
    for (int rr = 0; rr < 2; rr++) {
        int grow = row0 + w * 16 + g + rr * 8;
        if (grow >= N) continue;
#pragma unroll
        for (int j = 0; j < 8; j++) {
            int cx = j * 8 + q * 2;
            *(__half2*)(dst + (size_t)grow * 64 + cx) =
                __floats2half2_rn(c[j][rr * 2 + 0], c[j][rr * 2 + 1]);
        }
    }
}

// ---------------- setup kernels ----------------
__global__ void k_copy_init(const float* __restrict__ xglob, float* __restrict__ xg, int N) {
    int i = blockIdx.x * blockDim.x + threadIdx.x;
    if (i < NGR * DD) xg[i] = xglob[i];
    if (i < N) { g_deg[i] = 0; g_cursor[i] = 0; }
    if (i == 0) g_counter = 0;
}

__global__ void k_deg(const int* __restrict__ ei, int E) {
    int e = blockIdx.x * blockDim.x + threadIdx.x;
    if (e < E) atomicAdd(&g_deg[ei[E + e]], 1);
}

__global__ void k_alloc(int N) {
    int n = blockIdx.x * blockDim.x + threadIdx.x;
    unsigned m = 0xffffffffu;
    int lane = threadIdx.x & 31;
    int d = (n < N) ? g_deg[n] : 0;
    int s = d;
#pragma unroll
    for (int o = 1; o < 32; o <<= 1) {
        int t = __shfl_up_sync(m, s, o);
        if (lane >= o) s += t;
    }
    int base = 0;
    if (lane == 31) base = atomicAdd(&g_counter, s);
    base = __shfl_sync(m, base, 31);
    if (n < N) g_offs[n] = base + s - d;
}

__global__ void k_fill(const int* __restrict__ ei, int E) {
    int e = blockIdx.x * blockDim.x + threadIdx.x;
    if (e >= E) return;
    int dst = ei[E + e];
    int p = atomicAdd(&g_cursor[dst], 1);
    g_src[g_offs[dst] + p] = ei[e];
}

__global__ void k_convW(const float* __restrict__ Wa, const float* __restrict__ Wf,
                        const float* __restrict__ Wm) {
    int s = blockIdx.x >> 2, m = blockIdx.x & 3;
    const float* src;
    if (m == 0)      src = Wa + (size_t)s * 192 * 64;
    else if (m == 1) src = Wa + (size_t)s * 192 * 64 + 128 * 64;
    else if (m == 2) src = Wf + (size_t)s * 4096;
    else             src = Wm + (size_t)s * 4096;
    __nv_bfloat16* dh = (__nv_bfloat16*)&g_wimg[s][m][0];
    __nv_bfloat16* dl = dh + 4608;
    for (int idx = threadIdx.x; idx < 4096; idx += 128) {
        int n = idx >> 6, k = idx & 63;
        float v = src[k * 64 + n];           // B[n][k] = W^T
        __nv_bfloat16 h = __float2bfloat16_rn(v);
        dh[n * SA + k] = h;
        dl[n * SA + k] = __float2bfloat16_rn(v - __bfloat162float(h));
    }
}

// ---------------- per-step small kernels ----------------
__global__ void k_init_step(const float* __restrict__ xglob, const float* __restrict__ Wa_g) {
    int t = threadIdx.x;
    if (t < NGR) g_denom[t] = 0.f;
    g_numvec[t] = 0.f;
    int g = t >> 6, c = t & 63;
    float s = 0.f;
#pragma unroll 8
    for (int k = 0; k < 64; k++) s = fmaf(xglob[g * 64 + k], Wa_g[k * 64 + c], s);
    g_P[t] = s;
}

// agg gather over fp16 y: one half2 (4B) per lane per edge
__device__ __forceinline__ void agg_node(const float* bm_i, int n, int lane) {
    int off = g_offs[n], d = g_deg[n];
    const __half2* y2 = (const __half2*)g_y;
    __half2 m = __float2half2_rn(-INFINITY);
#pragma unroll 4
    for (int j = 0; j < d; j++) {
        int s = g_src[off + j];
        m = __hmax2(m, y2[(size_t)s * 32 + lane]);
    }
    float2 mf = __half22float2(m);
    float a0 = 0.f, a1 = 0.f;
    if (d > 0) {
        a0 = lrelu(mf.x + bm_i[2 * lane]);
        a1 = lrelu(mf.y + bm_i[2 * lane + 1]);
    }
    *(float2*)(g_agg + (size_t)n * 64 + 2 * lane) = make_float2(a0, a1);
}

// standalone agg (step 0 only)
__global__ void k_agg(const float* __restrict__ bm_i, int N) {
    int wid = threadIdx.x >> 5, lane = threadIdx.x & 31;
    int n = blockIdx.x * 8 + wid;
    if (n >= N) return;
    agg_node(bm_i, n, lane);
}

// agg(next step) blocks + ONE finalizer block (x_global update + next P/reset).
// numvec/denom are complete when this launch starts (k_fused accumulated them).
__global__ void k_aggB(const float* __restrict__ bm_next, int aggBlocks, int N,
                       float* __restrict__ xglob, const float* __restrict__ Wt_i,
                       const float* __restrict__ bt_i,
                       const float* __restrict__ Wa_g_next, int has_next) {
    if ((int)blockIdx.x < aggBlocks) {
        int wid = threadIdx.x >> 5, lane = threadIdx.x & 31;
        int n = (int)blockIdx.x * 8 + wid;
        if (n >= N) return;
        agg_node(bm_next, n, lane);
        return;
    }
    // ---- finalizer block ----
    __shared__ float cat[NGR * 128];
    __shared__ float xgn[NGR * 64];
    int t = threadIdx.x;
    for (int i = t; i < NGR * 64; i += 256) {
        int g = i >> 6, c = i & 63;
        cat[g * 128 + c] = g_numvec[i] / g_denom[g];
        cat[g * 128 + 64 + c] = xglob[i];
    }
    __syncthreads();
    for (int i = t; i < NGR * 64; i += 256) {
        int g = i >> 6, c = i & 63;
        float s = bt_i[c];
#pragma unroll 8
        for (int k = 0; k < 128; k++) s = fmaf(cat[g * 128 + k], Wt_i[k * 64 + c], s);
        s = lrelu(s) + cat[g * 128 + 64 + c];
        xglob[i] = s;
        xgn[i] = s;
    }
    if (!has_next) return;
    __syncthreads();
    if (t < NGR) g_denom[t] = 0.f;
    for (int i = t; i < NGR * 64; i += 256) {
        int g = i >> 6, c = i & 63;
        g_numvec[i] = 0.f;
        float p = 0.f;
#pragma unroll 8
        for (int k = 0; k < 64; k++) p = fmaf(xgn[g * 64 + k], Wa_g_next[k * 64 + c], p);
        g_P[i] = p;
    }
}

// ---------------- tensor GEMM kernels ----------------
__global__ void __launch_bounds__(TB, 2) k_gemm_y(const float* __restrict__ xin, int N) {
    extern __shared__ char dsm[];
    __nv_bfloat16* Ahi = (__nv_bfloat16*)(dsm + 0);
    __nv_bfloat16* Alo = (__nv_bfloat16*)(dsm + 18432);
    __nv_bfloat16* Whi = (__nv_bfloat16*)(dsm + 36864);
    __nv_bfloat16* Wlo = (__nv_bfloat16*)(dsm + 46080);
    int t = threadIdx.x, w = t >> 5, lane = t & 31;
    int row0 = blockIdx.x * TR;
    int cr = t >> 1, ch = t & 1;
    load_wimg_ca(&g_wimg[0][3][0], sptr(Whi), sptr(Wlo), t);
    CP_COMMIT();
    conv_g(xin + (size_t)(row0 + cr) * 64, Ahi, Alo, cr, ch, row0 + cr < N);
    CP_WAIT0();
    __syncthreads();
    float c[8][4];
    zero_c(c);
    gemm3(Ahi, Alo, Whi, Wlo, w, lane, c);
    store_ch(g_y, row0, w, lane, c, N);
}

// fused node kernel: x-update -> gate/e -> feat (accumulated into softmax buckets)
//                    -> y_next.  passB is absorbed (max-free segment softmax).
__global__ void __launch_bounds__(TB, 2) k_fused(
    const float* __restrict__ xin, float* __restrict__ xw,
    const int* __restrict__ batch,
    const float* __restrict__ ba_i, const float* __restrict__ bf_i,
    const float* __restrict__ Wg_i, const float* __restrict__ bg_i,
    int step, int has_next, int N) {
    extern __shared__ char dsm[];
    __nv_bfloat16* A0hi = (__nv_bfloat16*)(dsm + OFF_A0HI);
    __nv_bfloat16* A0lo = (__nv_bfloat16*)(dsm + OFF_A0LO);
    __nv_bfloat16* A1hi = (__nv_bfloat16*)(dsm + OFF_A1HI);
    __nv_bfloat16* A1lo = (__nv_bfloat16*)(dsm + OFF_A1LO);
    __nv_bfloat16* W0hi = (__nv_bfloat16*)(dsm + OFF_W0HI);
    __nv_bfloat16* W0lo = (__nv_bfloat16*)(dsm + OFF_W0LO);
    __nv_bfloat16* W1hi = (__nv_bfloat16*)(dsm + OFF_W1HI);
    __nv_bfloat16* W1lo = (__nv_bfloat16*)(dsm + OFF_W1LO);
    // softmax buckets alias the A1 tile space (dead after phase 1b)
    float* nv = (float*)(dsm + OFF_A1HI);            // [NGR*64]
    float* dn = (float*)(dsm + OFF_A1HI + 4096);     // [NGR]
    __shared__ float bas[64], bfs[64], wgs[64];
    int t = threadIdx.x, w = t >> 5, lane = t & 31;
    int g = lane >> 2, q = lane & 3;
    int row0 = blockIdx.x * TR;
    int cr = t >> 1, ch = t & 1;
    bool cv = row0 + cr < N;

    if (t < 64) { bas[t] = ba_i[t]; bfs[t] = bf_i[t]; wgs[t] = Wg_i[t]; }
    float bg0 = bg_i[0];

    load_wimg_ca(&g_wimg[step][0][0], sptr(W0hi), sptr(W0lo), t);
    load_wimg_ca(&g_wimg[step][1][0], sptr(W1hi), sptr(W1lo), t);
    CP_COMMIT();
    conv_g(xin + (size_t)(row0 + cr) * 64, A0hi, A0lo, cr, ch, cv);
    conv_g(g_agg + (size_t)(row0 + cr) * 64, A1hi, A1lo, cr, ch, cv);
    CP_WAIT0();
    __syncthreads();                       // sync 1: A tiles + W0/W1 visible

    float c[8][4];
    zero_c(c);
    gemm3(A0hi, A0lo, W0hi, W0lo, w, lane, c);   // x @ Wa_x
    gemm3(A1hi, A1lo, W1hi, W1lo, w, lane, c);   // + agg @ Wa_a
    __syncthreads();                       // sync 2: W0/W1 + A1 reads done

    // A1 space is dead -> init softmax buckets; prefetch W(feat)/W(y_next)
    for (int i = t; i < NGR * 64; i += TB) nv[i] = 0.f;
    if (t < NGR) dn[t] = 0.f;
    load_wimg_ca(&g_wimg[step][2][0], sptr(W0hi), sptr(W0lo), t);
    if (has_next) load_wimg_ca(&g_wimg[(step + 1) & 3][3][0], sptr(W1hi), sptr(W1lo), t);
    CP_COMMIT();

    // epilogue: x_new = lrelu(c + P[b] + ba) + x_old; e = exp(gate); re-split to A0
    float e_rr[2];
    int b_rr[2];
#pragma unroll
    for (int rr = 0; rr < 2; rr++) {
        int r = w * 16 + g + rr * 8;
        int grow = row0 + r;
        bool rv = grow < N;
        int b = batch[rv ? grow : N - 1];
        b_rr[rr] = b;
        float gate = 0.f;
#pragma unroll
        for (int j = 0; j < 8; j++) {
            int cx = j * 8 + q * 2;
            float v0 = c[j][rr * 2 + 0], v1 = c[j][rr * 2 + 1];
            float2 xo = rv ? *(const float2*)(xin + (size_t)grow * 64 + cx)
                           : make_float2(0.f, 0.f);
            float2 Pv = *(const float2*)(g_P + b * 64 + cx);
            v0 = lrelu(v0 + Pv.x + bas[cx]) + xo.x;
            v1 = lrelu(v1 + Pv.y + bas[cx + 1]) + xo.y;
            if (rv) *(float2*)(xw + (size_t)grow * 64 + cx) = make_float2(v0, v1);
            gate = fmaf(v0, wgs[cx], gate);
            gate = fmaf(v1, wgs[cx + 1], gate);
            __nv_bfloat162 hp = __floats2bfloat162_rn(v0, v1);
            __nv_bfloat162 lp = __floats2bfloat162_rn(v0 - __bfloat162float(hp.x),
                                                      v1 - __bfloat162float(hp.y));
            *(uint32_t*)(A0hi + r * SA + cx) = *(uint32_t*)&hp;
            *(uint32_t*)(A0lo + r * SA + cx) = *(uint32_t*)&lp;
        }
        gate += __shfl_xor_sync(0xffffffffu, gate, 1);
        gate += __shfl_xor_sync(0xffffffffu, gate, 2);   // full sum in all quad lanes
        e_rr[rr] = rv ? expf(gate + bg0) : 0.f;
    }
    CP_WAIT0();
    __syncthreads();                       // sync 3: A0(x_new) + buckets + new W visible

    // feat = lrelu(x_new @ Wfeat + bf) -> accumulate e*feat into buckets
    zero_c(c);
    gemm3(A0hi, A0lo, W0hi, W0lo, w, lane, c);
#pragma unroll
    for (int rr = 0; rr < 2; rr++) {
        float e = e_rr[rr];
        int b = b_rr[rr];
#pragma unroll
        for (int j = 0; j < 8; j++) {
            int cx = j * 8 + q * 2;
            float f0 = lrelu(c[j][rr * 2 + 0] + bfs[cx]);
            float f1 = lrelu(c[j][rr * 2 + 1] + bfs[cx + 1]);
            atomicAdd(&nv[b * 64 + cx], e * f0);
            atomicAdd(&nv[b * 64 + cx + 1], e * f1);
        }
        if (q == 0) atomicAdd(&dn[b], e);
    }
    // y_next = x_new @ Wm(step+1)  (overlaps with bucket traffic)
    if (has_next) {
        zero_c(c);
        gemm3(A0hi, A0lo, W1hi, W1lo, w, lane, c);
        store_ch(g_y, row0, w, lane, c, N);
    }
    __syncthreads();                       // buckets complete
    // flush buckets: block rows span batch[row0] .. batch[last]
    int bmin = batch[row0];
    int bmax = batch[min(row0 + TR - 1, N - 1)];
    for (int bb = bmin; bb <= bmax; bb++) {
        if (t < 64) atomicAdd(&g_numvec[bb * 64 + t], nv[bb * 64 + t]);
        else if (t == 64) atomicAdd(&g_denom[bb], dn[bb]);
    }
}

// ---------------- launch ----------------
extern "C" void kernel_launch(void* const* d_in, const int* in_sizes, int n_in,
                              void* d_out, int out_size) {
    const float* x       = (const float*)d_in[0];
    const float* xglobal = (const float*)d_in[1];
    const int*   ei      = (const int*)d_in[3];
    const int*   batch   = (const int*)d_in[4];
    int base = (in_sizes[5] == 1) ? 6 : 5;
    const float* Wm    = (const float*)d_in[base + 0];
    const float* bm    = (const float*)d_in[base + 1];
    const float* Wa    = (const float*)d_in[base + 2];
    const float* ba    = (const float*)d_in[base + 3];
    const float* Wgate = (const float*)d_in[base + 4];
    const float* bgate = (const float*)d_in[base + 5];
    const float* Wfeat = (const float*)d_in[base + 6];
    const float* bfeat = (const float*)d_in[base + 7];
    const float* Wt    = (const float*)d_in[base + 8];
    const float* bt    = (const float*)d_in[base + 9];

    int N = in_sizes[0] / DD;
    int E = in_sizes[3] / 2;
    float* out = (float*)d_out;
    float* xw  = out;
    float* xg  = out + (size_t)N * DD;

    cudaFuncSetAttribute(k_gemm_y, cudaFuncAttributeMaxDynamicSharedMemorySize, DYN_Y);
    cudaFuncSetAttribute(k_fused, cudaFuncAttributeMaxDynamicSharedMemorySize, DYN_FUSED);

    int gb = (N + TR - 1) / TR;
    int aggBlocks = (N + 7) / 8;
    k_copy_init<<<(N + 255) / 256, 256>>>(xglobal, xg, N);         // 0
    k_deg<<<(E + 255) / 256, 256>>>(ei, E);                        // 1
    k_convW<<<16, 128>>>(Wa, Wfeat, Wm);                           // 2
    k_gemm_y<<<gb, TB, DYN_Y>>>(x, N);                             // 3 (ncu slot)
    k_alloc<<<(N + 255) / 256, 256>>>(N);                          // 4
    k_fill<<<(E + 255) / 256, 256>>>(ei, E);                       // 5
    k_init_step<<<1, 1024>>>(xglobal, Wa + (size_t)64 * 64);       // 6
    k_agg<<<aggBlocks, 256>>>(bm, N);                              // 7

    for (int i = 0; i < 4; i++) {
        const float* xin = (i == 0) ? x : xw;
        int hn = (i < 3) ? 1 : 0;
        k_fused<<<gb, TB, DYN_FUSED>>>(xin, xw, batch,
                                       ba + i * 64, bfeat + i * 64,
                                       Wgate + i * 64, bgate + i,
                                       i, hn, N);
        int grid = (hn ? aggBlocks : 0) + 1;
        const float* Wa_g_next = Wa + ((size_t)((i + 1) & 3) * 192 + 64) * 64;
        k_aggB<<<grid, 256>>>(bm + ((i + 1) & 3) * 64, hn ? aggBlocks : 0, N,
                              xg, Wt + (size_t)i * 128 * 64, bt + i * 64,
                              Wa_g_next, hn);
    }
}

// round 17
// speedup vs baseline: 1.3599x; 1.3599x over previous
#include <cuda_runtime.h>
#include <cuda_bf16.h>
#include <cuda_fp16.h>
#include <math.h>
#include <stdint.h>

#define NMAX 100000
#define EMAX 1600000
#define DD 64
#define NGR 16
#define TR 128
#define TB 256
#define SA 72              // bf16 row stride for A/W smem tiles

// k_fused dynamic smem: A0hi A0lo A1hi A1lo W0hi W0lo W1hi W1lo
#define OFF_A0HI 0
#define OFF_A0LO 18432
#define OFF_A1HI 36864
#define OFF_A1LO 55296
#define OFF_W0HI 73728
#define OFF_W0LO 82944
#define OFF_W1HI 92160
#define OFF_W1LO 101376
#define DYN_FUSED 110592
#define DYN_Y 55296

// ---------------- device scratch ----------------
__device__ __half g_y[(size_t)NMAX * DD];     // fp16 messages
__device__ float g_agg[(size_t)NMAX * DD];
__device__ float g_feat[(size_t)NMAX * DD];
__device__ float g_gate[NMAX];
__device__ int   g_deg[NMAX];
__device__ int   g_offs[NMAX];
__device__ int   g_cursor[NMAX];
__device__ int   g_src[EMAX];
__device__ int   g_counter;
__device__ float g_P[NGR * DD];
__device__ float g_numvec[NGR * DD];
__device__ float g_denom[NGR];
__device__ int   g_gmax[NGR];
// weight images: [step][mat][hi 576 uint4 | lo 576 uint4]; mat: 0=Wa_x 1=Wa_a 2=Wfeat 3=Wm
__device__ uint4 g_wimg[4][4][1152];

__device__ __forceinline__ float lrelu(float v) { return v > 0.f ? v : 0.01f * v; }
__device__ __forceinline__ int   ordInt(float f) { int i = __float_as_int(f); return i >= 0 ? i : i ^ 0x7FFFFFFF; }
__device__ __forceinline__ float ordFloat(int i) { return __int_as_float(i >= 0 ? i : i ^ 0x7FFFFFFF); }

__device__ __forceinline__ uint32_t sptr(const void* p) {
    uint32_t a;
    asm("{ .reg .u64 t; cvta.to.shared.u64 t, %1; cvt.u32.u64 %0, t; }" : "=r"(a) : "l"(p));
    return a;
}
__device__ __forceinline__ void cp16(uint32_t saddr, const void* gaddr) {
    asm volatile("cp.async.cg.shared.global [%0], [%1], 16;" :: "r"(saddr), "l"(gaddr));
}
#define CP_COMMIT() asm volatile("cp.async.commit_group;" ::: "memory")
#define CP_WAIT0()  asm volatile("cp.async.wait_group 0;" ::: "memory")

// ---------------- mma.sync building blocks ----------------
__device__ __forceinline__ void mma16816(float c[4], uint32_t a0, uint32_t a1,
                                         uint32_t a2, uint32_t a3,
                                         uint32_t b0, uint32_t b1) {
    asm volatile(
        "mma.sync.aligned.m16n8k16.row.col.f32.bf16.bf16.f32 "
        "{%0,%1,%2,%3}, {%4,%5,%6,%7}, {%8,%9}, {%0,%1,%2,%3};"
        : "+f"(c[0]), "+f"(c[1]), "+f"(c[2]), "+f"(c[3])
        : "r"(a0), "r"(a1), "r"(a2), "r"(a3), "r"(b0), "r"(b1));
}

// warp w computes rows w*16..w*16+15 x all 64 cols: c[8][4]   (R13 core)
__device__ __forceinline__ void wgemm(const __nv_bfloat16* A, const __nv_bfloat16* W,
                                      int w, int lane, float c[8][4]) {
#pragma unroll
    for (int kt = 0; kt < 64; kt += 16) {
        int kk = kt + ((lane & 3) << 1);
        uint32_t b0[8], b1[8];
#pragma unroll
        for (int j = 0; j < 8; j++) {
            int n = j * 8 + (lane >> 2);
            b0[j] = *(const uint32_t*)(W + n * SA + kk);
            b1[j] = *(const uint32_t*)(W + n * SA + kk + 8);
        }
        int r = w * 16 + (lane >> 2);
        uint32_t a0 = *(const uint32_t*)(A + r * SA + kk);
        uint32_t a1 = *(const uint32_t*)(A + (r + 8) * SA + kk);
        uint32_t a2 = *(const uint32_t*)(A + r * SA + kk + 8);
        uint32_t a3 = *(const uint32_t*)(A + (r + 8) * SA + kk + 8);
#pragma unroll
        for (int j = 0; j < 8; j++) mma16816(c[j], a0, a1, a2, a3, b0[j], b1[j]);
    }
}

__device__ __forceinline__ void gemm3(const __nv_bfloat16* Ahi, const __nv_bfloat16* Alo,
                                      const __nv_bfloat16* Whi, const __nv_bfloat16* Wlo,
                                      int w, int lane, float c[8][4]) {
    wgemm(Ahi, Whi, w, lane, c);
    wgemm(Alo, Whi, w, lane, c);
    wgemm(Ahi, Wlo, w, lane, c);
}

__device__ __forceinline__ void zero_c(float c[8][4]) {
#pragma unroll
    for (int j = 0; j < 8; j++)
#pragma unroll
        for (int q = 0; q < 4; q++) c[j][q] = 0.f;
}

// stream-convert half a global fp32 row into bf16 hi/lo smem (row r, half h)
__device__ __forceinline__ void conv_g(const float* src, __nv_bfloat16* Ahi,
                                       __nv_bfloat16* Alo, int r, int h, bool valid) {
#pragma unroll
    for (int qq = h * 4; qq < h * 4 + 4; qq++) {
        float v[8];
        if (valid) {
            float4 a = ((const float4*)src)[qq * 2];
            float4 b = ((const float4*)src)[qq * 2 + 1];
            v[0] = a.x; v[1] = a.y; v[2] = a.z; v[3] = a.w;
            v[4] = b.x; v[5] = b.y; v[6] = b.z; v[7] = b.w;
        } else {
#pragma unroll
            for (int i = 0; i < 8; i++) v[i] = 0.f;
        }
        uint32_t hh[4], ll[4];
#pragma unroll
        for (int j = 0; j < 4; j++) {
            __nv_bfloat162 hp = __floats2bfloat162_rn(v[2 * j], v[2 * j + 1]);
            hh[j] = *(uint32_t*)&hp;
            __nv_bfloat162 lp = __floats2bfloat162_rn(v[2 * j] - __bfloat162float(hp.x),
                                                      v[2 * j + 1] - __bfloat162float(hp.y));
            ll[j] = *(uint32_t*)&lp;
        }
        *(uint4*)(Ahi + r * SA + qq * 8) = make_uint4(hh[0], hh[1], hh[2], hh[3]);
        *(uint4*)(Alo + r * SA + qq * 8) = make_uint4(ll[0], ll[1], ll[2], ll[3]);
    }
}

// async W image load (hi 576 + lo 576 uint4)
__device__ __forceinline__ void load_wimg_ca(const uint4* img, uint32_t wHi, uint32_t wLo, int t) {
    for (int i = t; i < 576; i += TB) {
        cp16(wHi + i * 16, img + i);
        cp16(wLo + i * 16, img + 576 + i);
    }
}

// direct fragment -> fp32 global store (optional bias+lrelu); warp w rows w*16+g, +8
__device__ __forceinline__ void store_c(float* dst, int row0, int w, int lane,
                                        float c[8][4], const float* bias, int N) {
    int g = lane >> 2, q = lane & 3;
#pragma unroll
    for (int rr = 0; rr < 2; rr++) {
        int grow = row0 + w * 16 + g + rr * 8;
        if (grow >= N) continue;
#pragma unroll
        for (int j = 0; j < 8; j++) {
            int cx = j * 8 + q * 2;
            float v0 = c[j][rr * 2 + 0], v1 = c[j][rr * 2 + 1];
            if (bias) { v0 = lrelu(v0 + bias[cx]); v1 = lrelu(v1 + bias[cx + 1]); }
            *(float2*)(dst + (size_t)grow * 64 + cx) = make_float2(v0, v1);
        }
    }
}

// fragment -> fp16 global store
__device__ __forceinline__ void store_ch(__half* dst, int row0, int w, int lane,
                                         float c[8][4], int N) {
    int g = lane >> 2, q = lane & 3;
#pragma unroll
    for (int rr = 0; rr < 2; rr++) {
        int grow = row0 + w * 16 + g + rr * 8;
        if (grow >= N) continue;
#pragma unroll
        for (int j = 0; j < 8; j++) {
            int cx = j * 8 + q * 2;
            *(__half2*)(dst + (size_t)grow * 64 + cx) =
                __floats2half2_rn(c[j][rr * 2 + 0], c[j][rr * 2 + 1]);
        }
    }
}

// ---------------- setup kernels ----------------
__global__ void k_copy_init(const float* __restrict__ xglob, float* __restrict__ xg, int N) {
    int i = blockIdx.x * blockDim.x + threadIdx.x;
    if (i < NGR * DD) xg[i] = xglob[i];
    if (i < N) { g_deg[i] = 0; g_cursor[i] = 0; }
    if (i == 0) g_counter = 0;
}

__global__ void k_deg(const int* __restrict__ ei, int E) {
    int e = blockIdx.x * blockDim.x + threadIdx.x;
    if (e < E) atomicAdd(&g_deg[ei[E + e]], 1);
}

__global__ void k_alloc(int N) {
    int n = blockIdx.x * blockDim.x + threadIdx.x;
    unsigned m = 0xffffffffu;
    int lane = threadIdx.x & 31;
    int d = (n < N) ? g_deg[n] : 0;
    int s = d;
#pragma unroll
    for (int o = 1; o < 32; o <<= 1) {
        int t = __shfl_up_sync(m, s, o);
        if (lane >= o) s += t;
    }
    int base = 0;
    if (lane == 31) base = atomicAdd(&g_counter, s);
    base = __shfl_sync(m, base, 31);
    if (n < N) g_offs[n] = base + s - d;
}

__global__ void k_fill(const int* __restrict__ ei, int E) {
    int e = blockIdx.x * blockDim.x + threadIdx.x;
    if (e >= E) return;
    int dst = ei[E + e];
    int p = atomicAdd(&g_cursor[dst], 1);
    g_src[g_offs[dst] + p] = ei[e];
}

__global__ void k_convW(const float* __restrict__ Wa, const float* __restrict__ Wf,
                        const float* __restrict__ Wm) {
    int s = blockIdx.x >> 2, m = blockIdx.x & 3;
    const float* src;
    if (m == 0)      src = Wa + (size_t)s * 192 * 64;
    else if (m == 1) src = Wa + (size_t)s * 192 * 64 + 128 * 64;
    else if (m == 2) src = Wf + (size_t)s * 4096;
    else             src = Wm + (size_t)s * 4096;
    __nv_bfloat16* dh = (__nv_bfloat16*)&g_wimg[s][m][0];
    __nv_bfloat16* dl = dh + 4608;
    for (int idx = threadIdx.x; idx < 4096; idx += 128) {
        int n = idx >> 6, k = idx & 63;
        float v = src[k * 64 + n];           // B[n][k] = W^T
        __nv_bfloat16 h = __float2bfloat16_rn(v);
        dh[n * SA + k] = h;
        dl[n * SA + k] = __float2bfloat16_rn(v - __bfloat162float(h));
    }
}

// ---------------- per-step small kernels ----------------
__global__ void k_init_step(const float* __restrict__ xglob, const float* __restrict__ Wa_g) {
    int t = threadIdx.x;
    if (t < NGR) { g_denom[t] = 0.f; g_gmax[t] = ordInt(-INFINITY); }
    g_numvec[t] = 0.f;
    int g = t >> 6, c = t & 63;
    float s = 0.f;
#pragma unroll 8
    for (int k = 0; k < 64; k++) s = fmaf(xglob[g * 64 + k], Wa_g[k * 64 + c], s);
    g_P[t] = s;
}

// agg gather over fp16 y: one half2 (4B) per lane per edge; unroll 8 for MLP
__device__ __forceinline__ void agg_node(const float* bm_i, int n, int lane) {
    int off = g_offs[n], d = g_deg[n];
    const __half2* y2 = (const __half2*)g_y;
    __half2 m = __float2half2_rn(-INFINITY);
    int j = 0;
#pragma unroll 1
    for (; j + 8 <= d; j += 8) {
        __half2 t0 = y2[(size_t)__ldg(&g_src[off + j + 0]) * 32 + lane];
        __half2 t1 = y2[(size_t)__ldg(&g_src[off + j + 1]) * 32 + lane];
        __half2 t2 = y2[(size_t)__ldg(&g_src[off + j + 2]) * 32 + lane];
        __half2 t3 = y2[(size_t)__ldg(&g_src[off + j + 3]) * 32 + lane];
        __half2 t4 = y2[(size_t)__ldg(&g_src[off + j + 4]) * 32 + lane];
        __half2 t5 = y2[(size_t)__ldg(&g_src[off + j + 5]) * 32 + lane];
        __half2 t6 = y2[(size_t)__ldg(&g_src[off + j + 6]) * 32 + lane];
        __half2 t7 = y2[(size_t)__ldg(&g_src[off + j + 7]) * 32 + lane];
        m = __hmax2(m, __hmax2(__hmax2(__hmax2(t0, t1), __hmax2(t2, t3)),
                               __hmax2(__hmax2(t4, t5), __hmax2(t6, t7))));
    }
    for (; j < d; j++)
        m = __hmax2(m, y2[(size_t)__ldg(&g_src[off + j]) * 32 + lane]);
    float2 mf = __half22float2(m);
    float a0 = 0.f, a1 = 0.f;
    if (d > 0) {
        a0 = lrelu(mf.x + bm_i[2 * lane]);
        a1 = lrelu(mf.y + bm_i[2 * lane + 1]);
    }
    *(float2*)(g_agg + (size_t)n * 64 + 2 * lane) = make_float2(a0, a1);
}

// standalone agg (step 0 only)
__global__ void k_agg(const float* __restrict__ bm_i, int N) {
    int wid = threadIdx.x >> 5, lane = threadIdx.x & 31;
    int n = blockIdx.x * 8 + wid;
    if (n >= N) return;
    agg_node(bm_i, n, lane);
}

// merged kernel: first pbBlocks do passB(step i); remaining blocks do agg(step i+1)
__global__ void k_aggB(const int* __restrict__ batch, const float* __restrict__ bm_next,
                       int pbBlocks, int N) {
    if ((int)blockIdx.x < pbBlocks) {
        int t = threadIdx.x;
        int tx = t & 63, ty = t >> 6;
        int base = blockIdx.x * 256;
        int nend = min(base + 256, N);
        float acc = 0.f, accd = 0.f;
        int gcur = -1;
        for (int n = base + ty; n < nend; n += 4) {
            int b = batch[n];
            if (b != gcur) {
                if (gcur >= 0) {
                    atomicAdd(&g_numvec[gcur * 64 + tx], acc);
                    if (tx == 0) atomicAdd(&g_denom[gcur], accd);
                }
                gcur = b; acc = 0.f; accd = 0.f;
            }
            float e = expf(g_gate[n] - ordFloat(g_gmax[b]));
            acc = fmaf(e, g_feat[(size_t)n * 64 + tx], acc);
            accd += e;
        }
        if (gcur >= 0) {
            atomicAdd(&g_numvec[gcur * 64 + tx], acc);
            if (tx == 0) atomicAdd(&g_denom[gcur], accd);
        }
    } else {
        int wid = threadIdx.x >> 5, lane = threadIdx.x & 31;
        int n = ((int)blockIdx.x - pbBlocks) * 8 + wid;
        if (n >= N) return;
        agg_node(bm_next, n, lane);
    }
}

// ---------------- tensor GEMM kernels ----------------
__global__ void __launch_bounds__(TB, 2) k_gemm_y(const float* __restrict__ xin, int N) {
    extern __shared__ char dsm[];
    __nv_bfloat16* Ahi = (__nv_bfloat16*)(dsm + 0);
    __nv_bfloat16* Alo = (__nv_bfloat16*)(dsm + 18432);
    __nv_bfloat16* Whi = (__nv_bfloat16*)(dsm + 36864);
    __nv_bfloat16* Wlo = (__nv_bfloat16*)(dsm + 46080);
    int t = threadIdx.x, w = t >> 5, lane = t & 31;
    int row0 = blockIdx.x * TR;
    int cr = t >> 1, ch = t & 1;
    load_wimg_ca(&g_wimg[0][3][0], sptr(Whi), sptr(Wlo), t);
    CP_COMMIT();
    conv_g(xin + (size_t)(row0 + cr) * 64, Ahi, Alo, cr, ch, row0 + cr < N);
    CP_WAIT0();
    __syncthreads();
    float c[8][4];
    zero_c(c);
    gemm3(Ahi, Alo, Whi, Wlo, w, lane, c);
    store_ch(g_y, row0, w, lane, c, N);
}

// fused node kernel, pipelined (R13 structure)
__global__ void __launch_bounds__(TB, 2) k_fused(
    const float* __restrict__ xin, float* __restrict__ xw,
    const int* __restrict__ batch,
    const float* __restrict__ ba_i, const float* __restrict__ bf_i,
    const float* __restrict__ Wg_i, const float* __restrict__ bg_i,
    int step, int has_next, int N) {
    extern __shared__ char dsm[];
    __nv_bfloat16* A0hi = (__nv_bfloat16*)(dsm + OFF_A0HI);
    __nv_bfloat16* A0lo = (__nv_bfloat16*)(dsm + OFF_A0LO);
    __nv_bfloat16* A1hi = (__nv_bfloat16*)(dsm + OFF_A1HI);
    __nv_bfloat16* A1lo = (__nv_bfloat16*)(dsm + OFF_A1LO);
    __nv_bfloat16* W0hi = (__nv_bfloat16*)(dsm + OFF_W0HI);
    __nv_bfloat16* W0lo = (__nv_bfloat16*)(dsm + OFF_W0LO);
    __nv_bfloat16* W1hi = (__nv_bfloat16*)(dsm + OFF_W1HI);
    __nv_bfloat16* W1lo = (__nv_bfloat16*)(dsm + OFF_W1LO);
    __shared__ float bas[64], bfs[64], wgs[64];
    __shared__ int gsm[NGR];
    int t = threadIdx.x, w = t >> 5, lane = t & 31;
    int g = lane >> 2, q = lane & 3;
    int row0 = blockIdx.x * TR;
    int cr = t >> 1, ch = t & 1;
    bool cv = row0 + cr < N;

    if (t < 64) { bas[t] = ba_i[t]; bfs[t] = bf_i[t]; wgs[t] = Wg_i[t]; }
    if (t < NGR) gsm[t] = ordInt(-INFINITY);
    float bg0 = bg_i[0];

    load_wimg_ca(&g_wimg[step][0][0], sptr(W0hi), sptr(W0lo), t);
    load_wimg_ca(&g_wimg[step][1][0], sptr(W1hi), sptr(W1lo), t);
    CP_COMMIT();
    conv_g(xin + (size_t)(row0 + cr) * 64, A0hi, A0lo, cr, ch, cv);
    conv_g(g_agg + (size_t)(row0 + cr) * 64, A1hi, A1lo, cr, ch, cv);
    CP_WAIT0();
    __syncthreads();                       // sync 1: A tiles + W0/W1 visible

    float c[8][4];
    zero_c(c);
    gemm3(A0hi, A0lo, W0hi, W0lo, w, lane, c);   // x @ Wa_x
    gemm3(A1hi, A1lo, W1hi, W1lo, w, lane, c);   // + agg @ Wa_a
    __syncthreads();                       // sync 2: all warps done reading W0/W1

    load_wimg_ca(&g_wimg[step][2][0], sptr(W0hi), sptr(W0lo), t);
    if (has_next) load_wimg_ca(&g_wimg[(step + 1) & 3][3][0], sptr(W1hi), sptr(W1lo), t);
    CP_COMMIT();

#pragma unroll
    for (int rr = 0; rr < 2; rr++) {
        int r = w * 16 + g + rr * 8;
        int grow = row0 + r;
        bool rv = grow < N;
        int b = batch[rv ? grow : N - 1];
        float gate = 0.f;
#pragma unroll
        for (int j = 0; j < 8; j++) {
            int cx = j * 8 + q * 2;
            float v0 = c[j][rr * 2 + 0], v1 = c[j][rr * 2 + 1];
            float2 xo = rv ? *(const float2*)(xin + (size_t)grow * 64 + cx)
                           : make_float2(0.f, 0.f);
            float2 Pv = *(const float2*)(g_P + b * 64 + cx);
            v0 = lrelu(v0 + Pv.x + bas[cx]) + xo.x;
            v1 = lrelu(v1 + Pv.y + bas[cx + 1]) + xo.y;
            if (rv) *(float2*)(xw + (size_t)grow * 64 + cx) = make_float2(v0, v1);
            gate = fmaf(v0, wgs[cx], gate);
            gate = fmaf(v1, wgs[cx + 1], gate);
            __nv_bfloat162 hp = __floats2bfloat162_rn(v0, v1);
            __nv_bfloat162 lp = __floats2bfloat162_rn(v0 - __bfloat162float(hp.x),
                                                      v1 - __bfloat162float(hp.y));
            *(uint32_t*)(A0hi + r * SA + cx) = *(uint32_t*)&hp;
            *(uint32_t*)(A0lo + r * SA + cx) = *(uint32_t*)&lp;
        }
        gate += __shfl_xor_sync(0xffffffffu, gate, 1);
        gate += __shfl_xor_sync(0xffffffffu, gate, 2);
        if (q == 0 && rv) {
            float gv = gate + bg0;
            g_gate[grow] = gv;
            atomicMax(&gsm[b], ordInt(gv));
        }
    }
    CP_WAIT0();
    __syncthreads();                       // sync 3: epilogue A0 + new W0/W1 visible
    if (t < NGR && gsm[t] != ordInt(-INFINITY)) atomicMax(&g_gmax[t], gsm[t]);

    zero_c(c);
    gemm3(A0hi, A0lo, W0hi, W0lo, w, lane, c);
    store_c(g_feat, row0, w, lane, c, bfs, N);
    if (has_next) {
        zero_c(c);
        gemm3(A0hi, A0lo, W1hi, W1lo, w, lane, c);
        store_ch(g_y, row0, w, lane, c, N);
    }
}

// x_global update + next-step P/reset. 1 block, 1024 threads.
__global__ void k_global(float* __restrict__ xglob, const float* __restrict__ Wt_i,
                         const float* __restrict__ bt_i,
                         const float* __restrict__ Wa_g_next, int has_next) {
    __shared__ float cat[NGR * 128];
    __shared__ float xgn[NGR * 64];
    int t = threadIdx.x;
    int g = t >> 6, c = t & 63;
    cat[g * 128 + c] = g_numvec[g * 64 + c] / g_denom[g];
    cat[g * 128 + 64 + c] = xglob[g * 64 + c];
    __syncthreads();
    float s = bt_i[c];
#pragma unroll 8
    for (int k = 0; k < 128; k++) s = fmaf(cat[g * 128 + k], Wt_i[k * 64 + c], s);
    s = lrelu(s) + cat[g * 128 + 64 + c];
    xglob[g * 64 + c] = s;
    xgn[g * 64 + c] = s;
    if (!has_next) return;
    __syncthreads();
    if (t < NGR) { g_denom[t] = 0.f; g_gmax[t] = ordInt(-INFINITY); }
    g_numvec[t] = 0.f;
    float p = 0.f;
#pragma unroll 8
    for (int k = 0; k < 64; k++) p = fmaf(xgn[g * 64 + k], Wa_g_next[k * 64 + c], p);
    g_P[t] = p;
}

// ---------------- launch ----------------
extern "C" void kernel_launch(void* const* d_in, const int* in_sizes, int n_in,
                              void* d_out, int out_size) {
    const float* x       = (const float*)d_in[0];
    const float* xglobal = (const float*)d_in[1];
    const int*   ei      = (const int*)d_in[3];
    const int*   batch   = (const int*)d_in[4];
    int base = (in_sizes[5] == 1) ? 6 : 5;
    const float* Wm    = (const float*)d_in[base + 0];
    const float* bm    = (const float*)d_in[base + 1];
    const float* Wa    = (const float*)d_in[base + 2];
    const float* ba    = (const float*)d_in[base + 3];
    const float* Wgate = (const float*)d_in[base + 4];
    const float* bgate = (const float*)d_in[base + 5];
    const float* Wfeat = (const float*)d_in[base + 6];
    const float* bfeat = (const float*)d_in[base + 7];
    const float* Wt    = (const float*)d_in[base + 8];
    const float* bt    = (const float*)d_in[base + 9];

    int N = in_sizes[0] / DD;
    int E = in_sizes[3] / 2;
    float* out = (float*)d_out;
    float* xw  = out;
    float* xg  = out + (size_t)N * DD;

    cudaFuncSetAttribute(k_gemm_y, cudaFuncAttributeMaxDynamicSharedMemorySize, DYN_Y);
    cudaFuncSetAttribute(k_fused, cudaFuncAttributeMaxDynamicSharedMemorySize, DYN_FUSED);

    int gb = (N + TR - 1) / TR;
    int pbBlocks = (N + 255) / 256;
    int aggBlocks = (N + 7) / 8;
    k_copy_init<<<(N + 255) / 256, 256>>>(xglobal, xg, N);         // 0
    k_deg<<<(E + 255) / 256, 256>>>(ei, E);                        // 1
    k_convW<<<16, 128>>>(Wa, Wfeat, Wm);                           // 2
    k_gemm_y<<<gb, TB, DYN_Y>>>(x, N);                             // 3 (ncu slot)
    k_alloc<<<(N + 255) / 256, 256>>>(N);                          // 4
    k_fill<<<(E + 255) / 256, 256>>>(ei, E);                       // 5
    k_init_step<<<1, 1024>>>(xglobal, Wa + (size_t)64 * 64);       // 6
    k_agg<<<aggBlocks, 256>>>(bm, N);                              // 7

    for (int i = 0; i < 4; i++) {
        const float* xin = (i == 0) ? x : xw;
        k_fused<<<gb, TB, DYN_FUSED>>>(xin, xw, batch,
                                       ba + i * 64, bfeat + i * 64,
                                       Wgate + i * 64, bgate + i,
                                       i, (i < 3) ? 1 : 0, N);
        int grid = pbBlocks + ((i < 3) ? aggBlocks : 0);
        k_aggB<<<grid, 256>>>(batch, bm + ((i + 1) & 3) * 64, pbBlocks, N);
        const float* Wa_g_next = Wa + ((size_t)((i + 1) & 3) * 192 + 64) * 64;
        k_global<<<1, 1024>>>(xg, Wt + (size_t)i * 128 * 64, bt + i * 64,
                              Wa_g_next, (i < 3) ? 1 : 0);
    }
}